// round 7
// baseline (speedup 1.0000x reference)
#include <cuda_runtime.h>
#include <math.h>

#define N_PIX 9216
#define C_DIM 64
#define BM 64
#define BN 64
#define NTILES (N_PIX / BN)   // 144

// Scratch (no cudaMalloc allowed): conv outputs in natural (C, HW) layout.
__device__ float g_y[C_DIM * N_PIX];   // dilated-conv output (q/k source)
__device__ float g_v[C_DIM * N_PIX];   // 1x1-conv output (v source)

// ---- packed f32x2 helpers (sm_103a FFMA2 path, bit-identical per lane) ----
__device__ __forceinline__ unsigned long long pack2(float lo, float hi) {
    unsigned long long r;
    asm("mov.b64 %0, {%1, %2};" : "=l"(r) : "f"(lo), "f"(hi));
    return r;
}
__device__ __forceinline__ float2 unpack2(unsigned long long v) {
    float2 f;
    asm("mov.b64 {%0, %1}, %2;" : "=f"(f.x), "=f"(f.y) : "l"(v));
    return f;
}
#define FMA2(d, a, b) asm("fma.rn.f32x2 %0, %1, %2, %0;" : "+l"(d) : "l"(a), "l"(b))
#define MUL2(d, a)    asm("mul.rn.f32x2 %0, %0, %1;"     : "+l"(d) : "l"(a))

// ---------------------------------------------------------------------------
// Dilated 3x3 conv, dilation=2, pad=2. One CTA per output row h, 512 threads:
// thread = (c_out, wslot of 8 x 12 outputs). f32x2-packed along w; x pairs
// come free as halves of LDS.128; weights software-pipelined to hide LDG.
// ---------------------------------------------------------------------------
__global__ void __launch_bounds__(512, 1)
dconv_kernel(const float* __restrict__ x,
             const float* __restrict__ dW,
             const float* __restrict__ db) {
    extern __shared__ float xs[];          // [3][64][100] (w padded 2 each side)
    const int ROWW = 100;
    int h = blockIdx.x;
    int tid = threadIdx.x;                 // 512 threads

    for (int i = tid; i < 3 * 64 * ROWW; i += 512) xs[i] = 0.f;
    __syncthreads();
    for (int i = tid; i < 3 * 64 * 96; i += 512) {
        int r   = i / (64 * 96);
        int rem = i % (64 * 96);
        int ci  = rem / 96;
        int w   = rem % 96;
        int hh  = h + 2 * (r - 1);
        if (hh >= 0 && hh < 96)
            xs[(r * 64 + ci) * ROWW + w + 2] = x[ci * N_PIX + hh * 96 + w];
    }
    __syncthreads();

    int c  = tid >> 3;                     // 0..63 output channel
    int w0 = (tid & 7) * 12;               // 12 outputs, 16B-aligned in xs

    unsigned long long acc2[6];
    {
        float b = __ldg(&db[c]);
#pragma unroll
        for (int k = 0; k < 6; k++) acc2[k] = pack2(b, b);
    }

    const float* wbase = &dW[c * 576];
    float wg[9];
#pragma unroll
    for (int t = 0; t < 9; t++) wg[t] = __ldg(&wbase[t]);

    for (int ci = 0; ci < 64; ci++) {
        float wgn[9];
        if (ci < 63) {
#pragma unroll
            for (int t = 0; t < 9; t++) wgn[t] = __ldg(&wbase[(ci + 1) * 9 + t]);
        }
#pragma unroll
        for (int r = 0; r < 3; r++) {
            const float* xr = &xs[(r * 64 + ci) * ROWW + w0];
            ulonglong2 xa = *reinterpret_cast<const ulonglong2*>(xr);
            ulonglong2 xb = *reinterpret_cast<const ulonglong2*>(xr + 4);
            ulonglong2 xc = *reinterpret_cast<const ulonglong2*>(xr + 8);
            ulonglong2 xd = *reinterpret_cast<const ulonglong2*>(xr + 12);
            unsigned long long px[8] = {xa.x, xa.y, xb.x, xb.y,
                                        xc.x, xc.y, xd.x, xd.y};
#pragma unroll
            for (int kw = 0; kw < 3; kw++) {
                unsigned long long wd = pack2(wg[r * 3 + kw], wg[r * 3 + kw]);
#pragma unroll
                for (int kp = 0; kp < 6; kp++) FMA2(acc2[kp], px[kp + kw], wd);
            }
        }
#pragma unroll
        for (int t = 0; t < 9; t++) wg[t] = wgn[t];
    }

    float* yo = &g_y[c * N_PIX + h * 96 + w0];
#pragma unroll
    for (int kp = 0; kp < 6; kp++) {
        float2 t = unpack2(acc2[kp]);
        yo[2 * kp]     = t.x;
        yo[2 * kp + 1] = t.y;
    }
}

// ---------------------------------------------------------------------------
// 1x1 conv: v[c][p] = cb[c] + sum_ci cW[c][ci] * x[ci][p]
// ---------------------------------------------------------------------------
__global__ void conv1x1_kernel(const float* __restrict__ x,
                               const float* __restrict__ cW,
                               const float* __restrict__ cb) {
    __shared__ float ws[64 * 64];
    int tid = threadIdx.x;                 // 128 threads
    for (int i = tid; i < 4096; i += 128) ws[i] = cW[i];
    __syncthreads();
    int p = blockIdx.x * 128 + tid;
#pragma unroll 1
    for (int chunk = 0; chunk < 4; chunk++) {
        float acc[16];
#pragma unroll
        for (int j = 0; j < 16; j++) acc[j] = __ldg(&cb[chunk * 16 + j]);
        for (int ci = 0; ci < 64; ci++) {
            float xv = x[ci * N_PIX + p];
#pragma unroll
            for (int j = 0; j < 16; j++)
                acc[j] += xv * ws[(chunk * 16 + j) * 64 + ci];
        }
#pragma unroll
        for (int j = 0; j < 16; j++)
            g_v[(chunk * 16 + j) * N_PIX + p] = acc[j];
    }
}

// ---------------------------------------------------------------------------
// Flash attention, fp32 with packed f32x2 FMAs.
//   Q/K staged c-pair-interleaved:  Qs[c2][n] = (q[2c2][n], q[2c2+1][n])
//   V   staged m-pair-interleaved:  Vs[m2][c] = (v[2m2][c], v[2m2+1][c])
//   P   staged row-major (m contiguous -> pairs free).
// 256 threads as 16x16, each thread owns a 4x4 microtile; S and O accumulate
// packed along the reduction dim, reduced lo+hi at tile end / epilogue.
// ---------------------------------------------------------------------------
__global__ void __launch_bounds__(256, 1)
attn_kernel(const float* __restrict__ x, float* __restrict__ out) {
    extern __shared__ float smem[];
    float* Qs = smem;                   // [32][66] float2 = 4224 floats
    float* Ks = Qs + 32 * 66 * 2;       // [32][66] float2
    float* Vs = Ks + 32 * 66 * 2;       // [32][66] float2
    float* Ps = Vs + 32 * 66 * 2;       // [64][68] floats

    int tid = threadIdx.x;
    int tx = tid & 15, ty = tid >> 4;
    int n0 = blockIdx.x * BM;

    // Stage Q transposed + c-pair-interleaved
    for (int i = tid; i < 1024; i += 256) {
        int n  = i >> 4;
        int c4 = (i & 15) * 4;
        float4 q = *reinterpret_cast<const float4*>(&g_y[(n0 + n) * 64 + c4]);
        int c2 = c4 >> 1;
        *reinterpret_cast<float2*>(&Qs[(c2 * 66 + n) * 2])       = make_float2(q.x, q.y);
        *reinterpret_cast<float2*>(&Qs[((c2 + 1) * 66 + n) * 2]) = make_float2(q.z, q.w);
    }

    unsigned long long O2[4][4];
    float mrow[4], lrow[4];
#pragma unroll
    for (int i = 0; i < 4; i++) {
        mrow[i] = -1e30f; lrow[i] = 0.f;
#pragma unroll
        for (int j = 0; j < 4; j++) O2[i][j] = 0ull;
    }
    __syncthreads();

    for (int t = 0; t < NTILES; t++) {
        int m0 = t * BN;
        // Stage K (c-pair interleaved) and V (m-pair interleaved)
        for (int i = tid; i < 512; i += 256) {
            int c2 = i >> 4;
            int mq = (i & 15) * 4;
            const float* kr = &g_y[(2 * c2) * N_PIX + m0 + mq];
            float4 a = *reinterpret_cast<const float4*>(kr);
            float4 b = *reinterpret_cast<const float4*>(kr + N_PIX);
            float* d = &Ks[(c2 * 66 + mq) * 2];
            reinterpret_cast<float4*>(d)[0] = make_float4(a.x, b.x, a.y, b.y);
            reinterpret_cast<float4*>(d)[1] = make_float4(a.z, b.z, a.w, b.w);
        }
        for (int i = tid; i < 512; i += 256) {
            int m2 = i >> 4;
            int cq = (i & 15) * 4;
            const float* vr = &g_v[(m0 + 2 * m2) * 64 + cq];
            float4 a = *reinterpret_cast<const float4*>(vr);
            float4 b = *reinterpret_cast<const float4*>(vr + 64);
            float* d = &Vs[(m2 * 66 + cq) * 2];
            reinterpret_cast<float4*>(d)[0] = make_float4(a.x, b.x, a.y, b.y);
            reinterpret_cast<float4*>(d)[1] = make_float4(a.z, b.z, a.w, b.w);
        }
        __syncthreads();

        // S = Q^T K, packed along c (2 c per FFMA2)
        unsigned long long s2[4][4];
#pragma unroll
        for (int i = 0; i < 4; i++)
#pragma unroll
            for (int j = 0; j < 4; j++) s2[i][j] = 0ull;

#pragma unroll 4
        for (int c2 = 0; c2 < 32; c2++) {
            const ulonglong2* qb =
                reinterpret_cast<const ulonglong2*>(&Qs[(c2 * 66 + ty * 4) * 2]);
            const ulonglong2* kb =
                reinterpret_cast<const ulonglong2*>(&Ks[(c2 * 66 + tx * 4) * 2]);
            ulonglong2 qA = qb[0], qB = qb[1];
            ulonglong2 kA = kb[0], kB = kb[1];
            unsigned long long qp[4] = {qA.x, qA.y, qB.x, qB.y};
            unsigned long long kp[4] = {kA.x, kA.y, kB.x, kB.y};
#pragma unroll
            for (int i = 0; i < 4; i++)
#pragma unroll
                for (int j = 0; j < 4; j++) FMA2(s2[i][j], qp[i], kp[j]);
        }

        // Reduce packed lanes, threshold (zeros stay in softmax!), row max
        float s[4][4];
        float tmax[4];
#pragma unroll
        for (int i = 0; i < 4; i++) {
            float mx = -1e30f;
#pragma unroll
            for (int j = 0; j < 4; j++) {
                float2 h2 = unpack2(s2[i][j]);
                float v = h2.x + h2.y;
                v = (fabsf(v) > 0.3f) ? v : 0.f;
                s[i][j] = v;
                mx = fmaxf(mx, v);
            }
            tmax[i] = mx;
        }
#pragma unroll
        for (int off = 8; off >= 1; off >>= 1)
#pragma unroll
            for (int i = 0; i < 4; i++)
                tmax[i] = fmaxf(tmax[i], __shfl_xor_sync(0xffffffffu, tmax[i], off, 16));

        // Online softmax update (O2 rescaled packed)
        float tsum[4];
#pragma unroll
        for (int i = 0; i < 4; i++) {
            float newm = fmaxf(mrow[i], tmax[i]);
            float corr = __expf(mrow[i] - newm);
            mrow[i] = newm;
            float sum = 0.f;
#pragma unroll
            for (int j = 0; j < 4; j++) {
                float p = __expf(s[i][j] - newm);
                s[i][j] = p;
                sum += p;
            }
            tsum[i] = sum;
            lrow[i] *= corr;
            unsigned long long cp = pack2(corr, corr);
#pragma unroll
            for (int j = 0; j < 4; j++) MUL2(O2[i][j], cp);
        }
#pragma unroll
        for (int off = 8; off >= 1; off >>= 1)
#pragma unroll
            for (int i = 0; i < 4; i++)
                tsum[i] += __shfl_xor_sync(0xffffffffu, tsum[i], off, 16);
#pragma unroll
        for (int i = 0; i < 4; i++) lrow[i] += tsum[i];

        // Stage P row-major (m contiguous)
#pragma unroll
        for (int i = 0; i < 4; i++)
            *reinterpret_cast<float4*>(&Ps[(ty * 4 + i) * 68 + tx * 4]) =
                make_float4(s[i][0], s[i][1], s[i][2], s[i][3]);
        __syncthreads();

        // O += P V, packed along m (P pairs free from float4 halves)
#pragma unroll 2
        for (int m = 0; m < 64; m += 4) {
            unsigned long long pp0[4], pp1[4];
#pragma unroll
            for (int i = 0; i < 4; i++) {
                ulonglong2 p = *reinterpret_cast<const ulonglong2*>(
                    &Ps[(ty * 4 + i) * 68 + m]);
                pp0[i] = p.x;   // (P[m],   P[m+1])
                pp1[i] = p.y;   // (P[m+2], P[m+3])
            }
            const ulonglong2* v0 = reinterpret_cast<const ulonglong2*>(
                &Vs[((m >> 1) * 66 + tx * 4) * 2]);
            const ulonglong2* v1 = reinterpret_cast<const ulonglong2*>(
                &Vs[(((m >> 1) + 1) * 66 + tx * 4) * 2]);
            ulonglong2 vA = v0[0], vB = v0[1];
            ulonglong2 vC = v1[0], vD = v1[1];
            unsigned long long vp0[4] = {vA.x, vA.y, vB.x, vB.y};
            unsigned long long vp1[4] = {vC.x, vC.y, vD.x, vD.y};
#pragma unroll
            for (int i = 0; i < 4; i++)
#pragma unroll
                for (int j = 0; j < 4; j++) {
                    FMA2(O2[i][j], pp0[i], vp0[j]);
                    FMA2(O2[i][j], pp1[i], vp1[j]);
                }
        }
        __syncthreads();   // protect Ks/Vs/Ps before next tile's loads
    }

    // Epilogue: out[c][n] = x[c][n] + (O2.lo + O2.hi)/l   (transposed scatter)
#pragma unroll
    for (int i = 0; i < 4; i++) {
        float inv = 1.f / lrow[i];
        int n = n0 + ty * 4 + i;
#pragma unroll
        for (int j = 0; j < 4; j++) {
            float2 o = unpack2(O2[i][j]);
            int c = tx * 4 + j;
            int idx = c * N_PIX + n;
            out[idx] = x[idx] + (o.x + o.y) * inv;
        }
    }
}

// ---------------------------------------------------------------------------
extern "C" void kernel_launch(void* const* d_in, const int* in_sizes, int n_in,
                              void* d_out, int out_size) {
    const float* x  = (const float*)d_in[0];
    const float* dW = (const float*)d_in[1];
    const float* db = (const float*)d_in[2];
    const float* cW = (const float*)d_in[3];
    const float* cb = (const float*)d_in[4];
    float* out = (float*)d_out;

    cudaFuncSetAttribute(dconv_kernel, cudaFuncAttributeMaxDynamicSharedMemorySize, 76800);
    cudaFuncSetAttribute(attn_kernel,  cudaFuncAttributeMaxDynamicSharedMemorySize, 69632);

    dconv_kernel<<<96, 512, 76800>>>(x, dW, db);
    conv1x1_kernel<<<72, 128>>>(x, cW, cb);
    attn_kernel<<<144, 256, 69632>>>(x, out);
}